// round 15
// baseline (speedup 1.0000x reference)
#include <cuda_runtime.h>
#include <cuda_fp16.h>
#include <cstdint>

#define BATCHN 64
#define FEAT   64
#define INF    64
#define NP     8
#define NCELL  256
#define NSYM   2048
#define NK2    9          // rfft half-plane: k2 in [0,8]
#define NFREQ  144        // 16 * 9
#define IPD    512        // INF * NP
#define IPD2   256        // IPD/2 (K-pairs)
#define FQD    512        // FEAT * NP

// -------- device scratch (no dynamic allocation allowed) --------
__device__ __half2 g_xf[(size_t)NFREQ * BATCHN * IPD];    // [k][b][ip] (re,im)
__device__ __half2 g_kf_re[(size_t)NFREQ * IPD2 * FQD];   // [k][ip/2][fq] (re ip-even, re ip-odd)
__device__ __half2 g_kf_im[(size_t)NFREQ * IPD2 * FQD];   // same for im
__device__ __half2 g_yf[(size_t)NFREQ * BATCHN * FQD];    // [k][b][fq] (re,im) fp16
__device__ unsigned short g_pt16[NP * NSYM];

// cos/sin of 2*pi*m/16 — __device__ constexpr: folded to FFMA immediates
__device__ constexpr float KC16[16] = {
    1.0f,  0.92387953251f,  0.70710678119f,  0.38268343236f,
    0.0f, -0.38268343236f, -0.70710678119f, -0.92387953251f,
   -1.0f, -0.92387953251f, -0.70710678119f, -0.38268343236f,
    0.0f,  0.38268343236f,  0.70710678119f,  0.92387953251f };
__device__ constexpr float KS16F[16] = {
    0.0f,  0.38268343236f,  0.70710678119f,  0.92387953251f,
    1.0f,  0.92387953251f,  0.70710678119f,  0.38268343236f,
    0.0f, -0.38268343236f, -0.70710678119f, -0.92387953251f,
   -1.0f, -0.92387953251f, -0.70710678119f, -0.38268343236f };

// runtime twiddles for k4 stageB hoist
__constant__ float CTW16[16] = {
    1.0f,  0.92387953251f,  0.70710678119f,  0.38268343236f,
    0.0f, -0.38268343236f, -0.70710678119f, -0.92387953251f,
   -1.0f, -0.92387953251f, -0.70710678119f, -0.38268343236f,
    0.0f,  0.38268343236f,  0.70710678119f,  0.92387953251f };
__constant__ float STW16[16] = {
    0.0f,  0.38268343236f,  0.70710678119f,  0.92387953251f,
    1.0f,  0.92387953251f,  0.70710678119f,  0.38268343236f,
    0.0f, -0.38268343236f, -0.70710678119f, -0.92387953251f,
   -1.0f, -0.92387953251f, -0.70710678119f, -0.38268343236f };

// ---------------- complex helpers + 16-point FFT (static twiddles) ----------
__device__ __forceinline__ float2 cadd(float2 a, float2 b){ return make_float2(a.x+b.x, a.y+b.y); }
__device__ __forceinline__ float2 csub(float2 a, float2 b){ return make_float2(a.x-b.x, a.y-b.y); }
__device__ __forceinline__ float2 cwf(float2 v, int m){   // v * e^{-2pi i m/16}
    float C = KC16[m & 15], S = KS16F[m & 15];
    return make_float2(v.x*C + v.y*S, v.y*C - v.x*S);
}
__device__ __forceinline__ float2 cwi(float2 v, int m){   // v * e^{+2pi i m/16}
    float C = KC16[m & 15], S = KS16F[m & 15];
    return make_float2(v.x*C - v.y*S, v.y*C + v.x*S);
}
__device__ __forceinline__ void dft4f(float2 a, float2 b, float2 c, float2 d, float2* A){
    float2 t0=cadd(a,c), t1=csub(a,c), t2=cadd(b,d), t3=csub(b,d);
    A[0]=cadd(t0,t2); A[2]=csub(t0,t2);
    A[1]=make_float2(t1.x + t3.y, t1.y - t3.x);
    A[3]=make_float2(t1.x - t3.y, t1.y + t3.x);
}
__device__ __forceinline__ void dft4i(float2 a, float2 b, float2 c, float2 d, float2* A){
    float2 t0=cadd(a,c), t1=csub(a,c), t2=cadd(b,d), t3=csub(b,d);
    A[0]=cadd(t0,t2); A[2]=csub(t0,t2);
    A[1]=make_float2(t1.x - t3.y, t1.y + t3.x);
    A[3]=make_float2(t1.x + t3.y, t1.y - t3.x);
}
template<bool INV>
__device__ __forceinline__ void cfft16(const float2* x, float2* X){
    float2 A[4], B[4], C4[4], D[4];
    if (!INV) {
        dft4f(x[0],x[4],x[8],x[12],A);  dft4f(x[2],x[6],x[10],x[14],B);
        dft4f(x[1],x[5],x[9],x[13],C4); dft4f(x[3],x[7],x[11],x[15],D);
    } else {
        dft4i(x[0],x[4],x[8],x[12],A);  dft4i(x[2],x[6],x[10],x[14],B);
        dft4i(x[1],x[5],x[9],x[13],C4); dft4i(x[3],x[7],x[11],x[15],D);
    }
    float2 E[8], O[8];
#pragma unroll
    for (int k = 0; k < 8; k++) {
        float2 tb = INV ? cwi(B[k&3], (2*k)&15) : cwf(B[k&3], (2*k)&15);
        float2 td = INV ? cwi(D[k&3], (2*k)&15) : cwf(D[k&3], (2*k)&15);
        E[k] = cadd(A[k&3], tb);
        O[k] = cadd(C4[k&3], td);
    }
#pragma unroll
    for (int k = 0; k < 16; k++) {
        float2 to = INV ? cwi(O[k&7], k&15) : cwf(O[k&7], k&15);
        X[k] = cadd(E[k&7], to);
    }
}

// ============ K0: product_table (int32 OR int64) -> uint16 ============
__global__ __launch_bounds__(256) void k0_pt(const void* __restrict__ pt_raw) {
    __shared__ int odd_nonzero;
    const int* p32 = (const int*)pt_raw;
    int tid = threadIdx.x;
    if (tid == 0) odd_nonzero = 0;
    __syncthreads();
    int local = 0;
    for (int t = tid; t < (NP * NSYM) / 2; t += 256) local |= p32[2 * t + 1];
    if (local) odd_nonzero = 1;
    __syncthreads();
    if (odd_nonzero) {
        for (int t = tid; t < NP * NSYM; t += 256)
            g_pt16[t] = (unsigned short)p32[t];
    } else {
        const long long* p64 = (const long long*)pt_raw;
        for (int t = tid; t < NP * NSYM; t += 256)
            g_pt16[t] = (unsigned short)p64[t];
    }
}

// ============ K1: forward rfft2 of x images (interleaved half2 out) ============
__global__ __launch_bounds__(256) void k1_xfft(const float* __restrict__ x) {
    int bi = blockIdx.x;
    int b  = bi >> 6;
    int i  = bi & 63;
    __shared__ float  xs2[NP][320];
    __shared__ float2 s1[NP][145];
    int tid = threadIdx.x;

    {
        const float4* xg = (const float4*)(x + (size_t)bi * NSYM);
        float4 a = xg[tid * 2], c = xg[tid * 2 + 1];
        int off = tid + (tid >> 4) * 4;
        xs2[0][off] = a.x; xs2[1][off] = a.y; xs2[2][off] = a.z; xs2[3][off] = a.w;
        xs2[4][off] = c.x; xs2[5][off] = c.y; xs2[6][off] = c.z; xs2[7][off] = c.w;
    }
    __syncthreads();

    {
        int k2h = tid >> 7, p = (tid >> 4) & 7, c1 = tid & 15;
        const float4* gp = (const float4*)&xs2[p][c1 * 20];
        float4 ga = gp[0], gb = gp[1], gc = gp[2], gd = gp[3];
        float g[16] = { ga.x, ga.y, ga.z, ga.w, gb.x, gb.y, gb.z, gb.w,
                        gc.x, gc.y, gc.z, gc.w, gd.x, gd.y, gd.z, gd.w };
        if (k2h == 0) {
            float ar[5] = {0,0,0,0,0}, ai[5] = {0,0,0,0,0};
#pragma unroll
            for (int c2 = 0; c2 < 16; c2++)
#pragma unroll
                for (int t = 0; t < 5; t++) {
                    const int id = ((t * c2) & 15);
                    ar[t] += g[c2] * KC16[id];
                    ai[t] -= g[c2] * KS16F[id];
                }
#pragma unroll
            for (int t = 0; t < 5; t++) s1[p][c1 * 9 + t] = make_float2(ar[t], ai[t]);
        } else {
            float ar[4] = {0,0,0,0}, ai[4] = {0,0,0,0};
#pragma unroll
            for (int c2 = 0; c2 < 16; c2++)
#pragma unroll
                for (int t = 0; t < 4; t++) {
                    const int id = (((t + 5) * c2) & 15);
                    ar[t] += g[c2] * KC16[id];
                    ai[t] -= g[c2] * KS16F[id];
                }
#pragma unroll
            for (int t = 0; t < 4; t++) s1[p][c1 * 9 + 5 + t] = make_float2(ar[t], ai[t]);
        }
    }
    __syncthreads();

    if (tid < 72) {
        int p = tid & 7, k2 = tid >> 3;
        float2 xin[16], Xo[16];
#pragma unroll
        for (int c1 = 0; c1 < 16; c1++) xin[c1] = s1[p][c1 * 9 + k2];
        cfft16<false>(xin, Xo);
#pragma unroll
        for (int k1 = 0; k1 < 16; k1++)
            g_xf[((size_t)(k1 * 9 + k2) * BATCHN + b) * IPD + (i << 3) + p] =
                __floats2half2_rn(Xo[k1].x, Xo[k1].y);
    }
}

// ============ K2: gather + forward rfft2; planar pair-packed output ============
// grid = 64*64*4 blocks; block = (f, i, p-pair).
__global__ __launch_bounds__(256) void k2_kfft(const float* __restrict__ kern) {
    int bx = blockIdx.x;
    int pp = bx & 3, fi = bx >> 2;
    int f  = fi >> 6, i = fi & 63;
    __shared__ float krow[NSYM];
    __shared__ unsigned short ptp[2][NSYM];
    __shared__ float  g8[2][NP][320];
    __shared__ float2 s1[2][NP][145];
    int tid = threadIdx.x;

    {
        const float4* kg = (const float4*)(kern + (size_t)fi * NSYM);
        ((float4*)krow)[tid * 2]     = kg[tid * 2];
        ((float4*)krow)[tid * 2 + 1] = kg[tid * 2 + 1];
        const uint4* pg = (const uint4*)(g_pt16 + (pp * 2) * NSYM);
        ((uint4*)ptp)[tid]       = pg[tid];
        ((uint4*)ptp)[tid + 256] = pg[tid + 256];
    }
    __syncthreads();

#pragma unroll
    for (int it = 0; it < 16; it++) {
        int idx = tid + (it << 8);
        int ph  = idx >> 11;
        int r   = idx & 2047;
        int q   = r & 7, d = r >> 3;
        g8[ph][q][d + (d >> 4) * 4] = krow[ptp[ph][r]];
    }
    __syncthreads();

    // stage1: thread = (ph, q, c1); direct real DFT, all 9 outputs
    {
        int ph = tid >> 7, q = (tid >> 4) & 7, c1 = tid & 15;
        const float4* gp = (const float4*)&g8[ph][q][c1 * 20];
        float4 ga = gp[0], gb = gp[1], gc = gp[2], gd = gp[3];
        float g[16] = { ga.x, ga.y, ga.z, ga.w, gb.x, gb.y, gb.z, gb.w,
                        gc.x, gc.y, gc.z, gc.w, gd.x, gd.y, gd.z, gd.w };
        float ar[9] = {0,0,0,0,0,0,0,0,0}, ai[9] = {0,0,0,0,0,0,0,0,0};
#pragma unroll
        for (int c2 = 0; c2 < 16; c2++)
#pragma unroll
            for (int t = 0; t < 9; t++) {
                const int id = ((t * c2) & 15);
                ar[t] += g[c2] * KC16[id];
                ai[t] -= g[c2] * KS16F[id];
            }
#pragma unroll
        for (int t = 0; t < 9; t++) s1[ph][q][c1 * 9 + t] = make_float2(ar[t], ai[t]);
    }
    __syncthreads();

    // stage2: thread = (q, k2), handles BOTH p-parities -> pair-packed planar store
    if (tid < 72) {
        int q = tid & 7, k2 = tid >> 3;
        float2 xin0[16], Xo0[16], xin1[16], Xo1[16];
#pragma unroll
        for (int c1 = 0; c1 < 16; c1++) { xin0[c1] = s1[0][q][c1 * 9 + k2];
                                          xin1[c1] = s1[1][q][c1 * 9 + k2]; }
        cfft16<false>(xin0, Xo0);
        cfft16<false>(xin1, Xo1);
#pragma unroll
        for (int k1 = 0; k1 < 16; k1++) {
            size_t a = ((size_t)(k1 * 9 + k2) * IPD2 + (i << 2) + pp) * FQD + (f << 3) + q;
            g_kf_re[a] = __floats2half2_rn(Xo0[k1].x, Xo1[k1].x);
            g_kf_im[a] = __floats2half2_rn(Xo0[k1].y, Xo1[k1].y);
        }
    }
}

// ============ K3: complex GEMM, fp16 mma, planar B, depth-4 cp.async ============
__device__ __forceinline__ void mma16(float* d, const uint32_t* a,
                                      uint32_t b0, uint32_t b1) {
    asm volatile(
        "mma.sync.aligned.m16n8k16.row.col.f32.f16.f16.f32 "
        "{%0,%1,%2,%3}, {%4,%5,%6,%7}, {%8,%9}, {%0,%1,%2,%3};\n"
        : "+f"(d[0]), "+f"(d[1]), "+f"(d[2]), "+f"(d[3])
        : "r"(a[0]), "r"(a[1]), "r"(a[2]), "r"(a[3]), "r"(b0), "r"(b1));
}
__device__ __forceinline__ void cpa16(uint32_t s, const void* g) {
    asm volatile("cp.async.cg.shared.global [%0], [%1], 16;" :: "r"(s), "l"(g));
}

__global__ __launch_bounds__(256) void k3_gemm_hmma() {
    int kidx = blockIdx.x;
    int n0   = blockIdx.y << 7;
    __shared__ __align__(16) __half2 Xs[4][64][20];    // interleaved (re,im)
    __shared__ __align__(16) __half2 Wr[4][8][132];    // (re even, re odd) K-pairs
    __shared__ __align__(16) __half2 Wi[4][8][132];    // (im even, im odd)

    int tid = threadIdx.x, wid = tid >> 5, lane = tid & 31;
    int wm = (wid & 3) << 4, wn = (wid >> 2) << 6;
    int gid = lane >> 2, tig = lane & 3;

    const __half2* Xg  = g_xf    + (size_t)kidx * BATCHN * IPD;
    const __half2* Wgr = g_kf_re + (size_t)kidx * IPD2 * FQD + n0;
    const __half2* Wgi = g_kf_im + (size_t)kidx * IPD2 * FQD + n0;

    int xb = tid >> 2, xseg = tid & 3;           // X staging (1 cpa)
    int wkp = tid >> 5, wseg = tid & 31;         // W staging (2 cpa: re+im)

    float accr[8][4], acci[8][4];
#pragma unroll
    for (int j = 0; j < 8; j++)
#pragma unroll
        for (int c = 0; c < 4; c++) { accr[j][c] = 0.f; acci[j][c] = 0.f; }

    // prefetch chunks 0..2
#pragma unroll
    for (int pc = 0; pc < 3; pc++) {
        int k0 = pc << 4, kp0 = pc << 3;
        cpa16((uint32_t)__cvta_generic_to_shared(&Xs[pc][xb][xseg * 4]),
              Xg + (size_t)xb * IPD + k0 + xseg * 4);
        cpa16((uint32_t)__cvta_generic_to_shared(&Wr[pc][wkp][wseg * 4]),
              Wgr + (size_t)(kp0 + wkp) * FQD + wseg * 4);
        cpa16((uint32_t)__cvta_generic_to_shared(&Wi[pc][wkp][wseg * 4]),
              Wgi + (size_t)(kp0 + wkp) * FQD + wseg * 4);
        asm volatile("cp.async.commit_group;");
    }

    for (int c = 0; c < 32; c++) {
        if (c + 3 < 32) {
            int nb = (c + 3) & 3, nk0 = (c + 3) << 4, nkp = (c + 3) << 3;
            cpa16((uint32_t)__cvta_generic_to_shared(&Xs[nb][xb][xseg * 4]),
                  Xg + (size_t)xb * IPD + nk0 + xseg * 4);
            cpa16((uint32_t)__cvta_generic_to_shared(&Wr[nb][wkp][wseg * 4]),
                  Wgr + (size_t)(nkp + wkp) * FQD + wseg * 4);
            cpa16((uint32_t)__cvta_generic_to_shared(&Wi[nb][wkp][wseg * 4]),
                  Wgi + (size_t)(nkp + wkp) * FQD + wseg * 4);
        }
        asm volatile("cp.async.commit_group;");
        asm volatile("cp.async.wait_group 3;");
        __syncthreads();

        int cb = c & 3;
        uint32_t arf[4], aif[4], ainf[4];
#pragma unroll
        for (int m = 0; m < 4; m++) {
            int row  = wm + gid + (m & 1) * 8;
            int kpos = 2 * tig + (m >> 1) * 8;
            uint2 lh = *(const uint2*)&Xs[cb][row][kpos];
            arf[m]  = __byte_perm(lh.x, lh.y, 0x5410);
            aif[m]  = __byte_perm(lh.x, lh.y, 0x7632);
            ainf[m] = aif[m] ^ 0x80008000u;          // -Xi
        }
#pragma unroll
        for (int j = 0; j < 8; j++) {
            int col = wn + (j << 3) + gid;
            uint32_t br0 = *(const uint32_t*)&Wr[cb][tig][col];
            uint32_t br1 = *(const uint32_t*)&Wr[cb][tig + 4][col];
            uint32_t bi0 = *(const uint32_t*)&Wi[cb][tig][col];
            uint32_t bi1 = *(const uint32_t*)&Wi[cb][tig + 4][col];
            mma16(accr[j], arf,  br0, br1);   // Yr += Xr*Wr
            mma16(accr[j], ainf, bi0, bi1);   // Yr += (-Xi)*Wi
            mma16(acci[j], arf,  bi0, bi1);   // Yi += Xr*Wi
            mma16(acci[j], aif,  br0, br1);   // Yi += Xi*Wr
        }
        __syncthreads();
    }

    __half2* Yg = g_yf + (size_t)kidx * BATCHN * FQD;
#pragma unroll
    for (int j = 0; j < 8; j++) {
        int nbase = n0 + wn + (j << 3) + 2 * tig;
        int r0 = wm + gid;
        int r1 = wm + gid + 8;
        Yg[(size_t)r0 * FQD + nbase]     = __floats2half2_rn(accr[j][0], acci[j][0]);
        Yg[(size_t)r0 * FQD + nbase + 1] = __floats2half2_rn(accr[j][1], acci[j][1]);
        Yg[(size_t)r1 * FQD + nbase]     = __floats2half2_rn(accr[j][2], acci[j][2]);
        Yg[(size_t)r1 * FQD + nbase + 1] = __floats2half2_rn(accr[j][3], acci[j][3]);
    }
}

// ============ K4: inverse rfft2 + bias; FFT stageA, hoisted stageB ============
__global__ __launch_bounds__(256) void k4_inv(const float* __restrict__ bias,
                                              float* __restrict__ out) {
    int bf = blockIdx.x;
    int b  = bf >> 6;
    int f  = bf & 63;
    __shared__ float2 ys[NP][145];
    __shared__ float2 T[NP][145];
    __shared__ float2 tw[16];
    int tid = threadIdx.x;
    if (tid < 16) tw[tid] = make_float2(CTW16[tid], STW16[tid]);

    for (int idx = tid; idx < NP * NFREQ; idx += 256) {
        int kidx = idx >> 3;
        int q    = idx & 7;
        ys[q][kidx] = __half22float2(
            g_yf[((size_t)kidx * BATCHN + b) * FQD + (f << 3) + q]);
    }
    __syncthreads();

    if (tid < 72) {
        int q = tid & 7, k2 = tid >> 3;
        float2 xin[16], Xo[16];
#pragma unroll
        for (int k1 = 0; k1 < 16; k1++) xin[k1] = ys[q][k1 * 9 + k2];
        cfft16<true>(xin, Xo);
#pragma unroll
        for (int c1 = 0; c1 < 16; c1++) T[q][c1 * 9 + k2] = Xo[c1];
    }
    __syncthreads();

    float bv = bias[f];
    {
        int q  = tid & 7;
        int c2 = (tid >> 3) & 15;
        float wc[9], ws[9];
#pragma unroll
        for (int k2 = 0; k2 < NK2; k2++) {
            float2 w = tw[(k2 * c2) & 15];
            float wt = (k2 == 0 || k2 == 8) ? (1.f / 256.f) : (2.f / 256.f);
            wc[k2] = wt * w.x;
            ws[k2] = wt * w.y;
        }
#pragma unroll
        for (int u = 0; u < 8; u++) {
            int c1 = u * 2 + (tid >> 7);
            float acc = bv;
#pragma unroll
            for (int k2 = 0; k2 < NK2; k2++) {
                float2 v = T[q][c1 * 9 + k2];
                acc += v.x * wc[k2] - v.y * ws[k2];
            }
            out[(size_t)bf * NSYM + u * 256 + tid] = acc;
        }
    }
}

// ============ launch ============
extern "C" void kernel_launch(void* const* d_in, const int* in_sizes, int n_in,
                              void* d_out, int out_size) {
    const float* x    = (const float*)d_in[0];
    const float* kern = (const float*)d_in[1];
    const float* bias = (const float*)d_in[2];
    const void*  pt   = d_in[3];              // int32 or int64 — k0 autodetects
    float*       out  = (float*)d_out;

    k0_pt<<<1, 256>>>(pt);
    k1_xfft<<<BATCHN * INF, 256>>>(x);
    k2_kfft<<<FEAT * INF * 4, 256>>>(kern);
    dim3 g3(NFREQ, FQD / 128);
    k3_gemm_hmma<<<g3, 256>>>();
    k4_inv<<<BATCHN * FEAT, 256>>>(bias, out);
}

// round 16
// speedup vs baseline: 1.0628x; 1.0628x over previous
#include <cuda_runtime.h>
#include <cuda_fp16.h>
#include <cstdint>

#define BATCHN 64
#define FEAT   64
#define INF    64
#define NP     8
#define NCELL  256
#define NSYM   2048
#define NK2    9          // rfft half-plane: k2 in [0,8]
#define NFREQ  144        // 16 * 9
#define IPD    512        // INF * NP
#define IPD2   256        // IPD/2 (K-pairs)
#define FQD    512        // FEAT * NP

// -------- device scratch (no dynamic allocation allowed) --------
__device__ __half2 g_xf[(size_t)NFREQ * BATCHN * IPD];    // [k][b][ip] (re,im)
__device__ __half2 g_kf_re[(size_t)NFREQ * IPD2 * FQD];   // [k][ip/2][fq]
__device__ __half2 g_kf_im[(size_t)NFREQ * IPD2 * FQD];
__device__ __half2 g_yf[(size_t)NFREQ * BATCHN * FQD];    // [k][b][fq]
__device__ unsigned short g_pt16[NP * NSYM];

__device__ constexpr float KC16[16] = {
    1.0f,  0.92387953251f,  0.70710678119f,  0.38268343236f,
    0.0f, -0.38268343236f, -0.70710678119f, -0.92387953251f,
   -1.0f, -0.92387953251f, -0.70710678119f, -0.38268343236f,
    0.0f,  0.38268343236f,  0.70710678119f,  0.92387953251f };
__device__ constexpr float KS16F[16] = {
    0.0f,  0.38268343236f,  0.70710678119f,  0.92387953251f,
    1.0f,  0.92387953251f,  0.70710678119f,  0.38268343236f,
    0.0f, -0.38268343236f, -0.70710678119f, -0.92387953251f,
   -1.0f, -0.92387953251f, -0.70710678119f, -0.38268343236f };

__constant__ float CTW16[16] = {
    1.0f,  0.92387953251f,  0.70710678119f,  0.38268343236f,
    0.0f, -0.38268343236f, -0.70710678119f, -0.92387953251f,
   -1.0f, -0.92387953251f, -0.70710678119f, -0.38268343236f,
    0.0f,  0.38268343236f,  0.70710678119f,  0.92387953251f };
__constant__ float STW16[16] = {
    0.0f,  0.38268343236f,  0.70710678119f,  0.92387953251f,
    1.0f,  0.92387953251f,  0.70710678119f,  0.38268343236f,
    0.0f, -0.38268343236f, -0.70710678119f, -0.92387953251f,
   -1.0f, -0.92387953251f, -0.70710678119f, -0.38268343236f };

// ---------------- complex helpers + 16-point FFT (static twiddles) ----------
__device__ __forceinline__ float2 cadd(float2 a, float2 b){ return make_float2(a.x+b.x, a.y+b.y); }
__device__ __forceinline__ float2 csub(float2 a, float2 b){ return make_float2(a.x-b.x, a.y-b.y); }
__device__ __forceinline__ float2 cwf(float2 v, int m){
    float C = KC16[m & 15], S = KS16F[m & 15];
    return make_float2(v.x*C + v.y*S, v.y*C - v.x*S);
}
__device__ __forceinline__ float2 cwi(float2 v, int m){
    float C = KC16[m & 15], S = KS16F[m & 15];
    return make_float2(v.x*C - v.y*S, v.y*C + v.x*S);
}
__device__ __forceinline__ void dft4f(float2 a, float2 b, float2 c, float2 d, float2* A){
    float2 t0=cadd(a,c), t1=csub(a,c), t2=cadd(b,d), t3=csub(b,d);
    A[0]=cadd(t0,t2); A[2]=csub(t0,t2);
    A[1]=make_float2(t1.x + t3.y, t1.y - t3.x);
    A[3]=make_float2(t1.x - t3.y, t1.y + t3.x);
}
__device__ __forceinline__ void dft4i(float2 a, float2 b, float2 c, float2 d, float2* A){
    float2 t0=cadd(a,c), t1=csub(a,c), t2=cadd(b,d), t3=csub(b,d);
    A[0]=cadd(t0,t2); A[2]=csub(t0,t2);
    A[1]=make_float2(t1.x - t3.y, t1.y + t3.x);
    A[3]=make_float2(t1.x + t3.y, t1.y - t3.x);
}
template<bool INV>
__device__ __forceinline__ void cfft16(const float2* x, float2* X){
    float2 A[4], B[4], C4[4], D[4];
    if (!INV) {
        dft4f(x[0],x[4],x[8],x[12],A);  dft4f(x[2],x[6],x[10],x[14],B);
        dft4f(x[1],x[5],x[9],x[13],C4); dft4f(x[3],x[7],x[11],x[15],D);
    } else {
        dft4i(x[0],x[4],x[8],x[12],A);  dft4i(x[2],x[6],x[10],x[14],B);
        dft4i(x[1],x[5],x[9],x[13],C4); dft4i(x[3],x[7],x[11],x[15],D);
    }
    float2 E[8], O[8];
#pragma unroll
    for (int k = 0; k < 8; k++) {
        float2 tb = INV ? cwi(B[k&3], (2*k)&15) : cwf(B[k&3], (2*k)&15);
        float2 td = INV ? cwi(D[k&3], (2*k)&15) : cwf(D[k&3], (2*k)&15);
        E[k] = cadd(A[k&3], tb);
        O[k] = cadd(C4[k&3], td);
    }
#pragma unroll
    for (int k = 0; k < 16; k++) {
        float2 to = INV ? cwi(O[k&7], k&15) : cwf(O[k&7], k&15);
        X[k] = cadd(E[k&7], to);
    }
}

// Pair-FFT stage1: rows ra/rb (16 reals each) -> 9-bin rffts of both via one cfft16.
__device__ __forceinline__ void rfft16_pair(const float* A, const float* Bv,
                                            float2* outA, float2* outB) {
    float2 z[16], Z[16];
#pragma unroll
    for (int c2 = 0; c2 < 16; c2++) z[c2] = make_float2(A[c2], Bv[c2]);
    cfft16<false>(z, Z);
#pragma unroll
    for (int k = 0; k < NK2; k++) {
        int m = (16 - k) & 15;
        float2 Pk = Z[k], Pm = Z[m];
        outA[k] = make_float2(0.5f * (Pk.x + Pm.x), 0.5f * (Pk.y - Pm.y));
        outB[k] = make_float2(0.5f * (Pk.y + Pm.y), 0.5f * (Pm.x - Pk.x));
    }
}

// ============ K0: product_table (int32 OR int64) -> uint16 ============
__global__ __launch_bounds__(256) void k0_pt(const void* __restrict__ pt_raw) {
    __shared__ int odd_nonzero;
    const int* p32 = (const int*)pt_raw;
    int tid = threadIdx.x;
    if (tid == 0) odd_nonzero = 0;
    __syncthreads();
    int local = 0;
    for (int t = tid; t < (NP * NSYM) / 2; t += 256) local |= p32[2 * t + 1];
    if (local) odd_nonzero = 1;
    __syncthreads();
    if (odd_nonzero) {
        for (int t = tid; t < NP * NSYM; t += 256)
            g_pt16[t] = (unsigned short)p32[t];
    } else {
        const long long* p64 = (const long long*)pt_raw;
        for (int t = tid; t < NP * NSYM; t += 256)
            g_pt16[t] = (unsigned short)p64[t];
    }
}

// ============ K1: forward rfft2 of x images (pair-FFT stage1) ============
__global__ __launch_bounds__(256) void k1_xfft(const float* __restrict__ x) {
    int bi = blockIdx.x;
    int b  = bi >> 6;
    int i  = bi & 63;
    __shared__ float  xs2[NP][320];    // [p][c1*20 + c2]
    __shared__ float2 s1[NP][145];
    int tid = threadIdx.x;

    {
        const float4* xg = (const float4*)(x + (size_t)bi * NSYM);
        float4 a = xg[tid * 2], c = xg[tid * 2 + 1];
        int off = tid + (tid >> 4) * 4;
        xs2[0][off] = a.x; xs2[1][off] = a.y; xs2[2][off] = a.z; xs2[3][off] = a.w;
        xs2[4][off] = c.x; xs2[5][off] = c.y; xs2[6][off] = c.z; xs2[7][off] = c.w;
    }
    __syncthreads();

    // stage1: thread = (p, c1-pair); one cfft16 for two real rows
    if (tid < 64) {
        int u = tid & 7, p = tid >> 3;
        const float4* ra = (const float4*)&xs2[p][(2 * u) * 20];
        const float4* rb = (const float4*)&xs2[p][(2 * u + 1) * 20];
        float4 a0=ra[0],a1=ra[1],a2=ra[2],a3=ra[3];
        float4 b0=rb[0],b1=rb[1],b2=rb[2],b3=rb[3];
        float A[16]  = {a0.x,a0.y,a0.z,a0.w,a1.x,a1.y,a1.z,a1.w,
                        a2.x,a2.y,a2.z,a2.w,a3.x,a3.y,a3.z,a3.w};
        float Bv[16] = {b0.x,b0.y,b0.z,b0.w,b1.x,b1.y,b1.z,b1.w,
                        b2.x,b2.y,b2.z,b2.w,b3.x,b3.y,b3.z,b3.w};
        float2 oa[NK2], ob[NK2];
        rfft16_pair(A, Bv, oa, ob);
#pragma unroll
        for (int k = 0; k < NK2; k++) {
            s1[p][(2 * u) * 9 + k]     = oa[k];
            s1[p][(2 * u + 1) * 9 + k] = ob[k];
        }
    }
    __syncthreads();

    // stage2: item = (p, k2): 16-pt FFT over c1
    if (tid < 72) {
        int p = tid & 7, k2 = tid >> 3;
        float2 xin[16], Xo[16];
#pragma unroll
        for (int c1 = 0; c1 < 16; c1++) xin[c1] = s1[p][c1 * 9 + k2];
        cfft16<false>(xin, Xo);
#pragma unroll
        for (int k1 = 0; k1 < 16; k1++)
            g_xf[((size_t)(k1 * 9 + k2) * BATCHN + b) * IPD + (i << 3) + p] =
                __floats2half2_rn(Xo[k1].x, Xo[k1].y);
    }
}

// ============ K2: gather + forward rfft2; pair-FFT stage1, planar output ======
__global__ __launch_bounds__(256) void k2_kfft(const float* __restrict__ kern) {
    int bx = blockIdx.x;
    int pp = bx & 3, fi = bx >> 2;
    int f  = fi >> 6, i = fi & 63;
    __shared__ float krow[NSYM];
    __shared__ unsigned short ptp[2][NSYM];
    __shared__ float  g8[2][NP][320];
    __shared__ float2 s1[2][NP][145];
    int tid = threadIdx.x;

    {
        const float4* kg = (const float4*)(kern + (size_t)fi * NSYM);
        ((float4*)krow)[tid * 2]     = kg[tid * 2];
        ((float4*)krow)[tid * 2 + 1] = kg[tid * 2 + 1];
        const uint4* pg = (const uint4*)(g_pt16 + (pp * 2) * NSYM);
        ((uint4*)ptp)[tid]       = pg[tid];
        ((uint4*)ptp)[tid + 256] = pg[tid + 256];
    }
    __syncthreads();

#pragma unroll
    for (int it = 0; it < 16; it++) {
        int idx = tid + (it << 8);
        int ph  = idx >> 11;
        int r   = idx & 2047;
        int q   = r & 7, d = r >> 3;
        g8[ph][q][d + (d >> 4) * 4] = krow[ptp[ph][r]];
    }
    __syncthreads();

    // stage1: thread = (ph, q, c1-pair); pair-FFT
    if (tid < 128) {
        int u = tid & 7, q = (tid >> 3) & 7, ph = tid >> 6;
        const float4* ra = (const float4*)&g8[ph][q][(2 * u) * 20];
        const float4* rb = (const float4*)&g8[ph][q][(2 * u + 1) * 20];
        float4 a0=ra[0],a1=ra[1],a2=ra[2],a3=ra[3];
        float4 b0=rb[0],b1=rb[1],b2=rb[2],b3=rb[3];
        float A[16]  = {a0.x,a0.y,a0.z,a0.w,a1.x,a1.y,a1.z,a1.w,
                        a2.x,a2.y,a2.z,a2.w,a3.x,a3.y,a3.z,a3.w};
        float Bv[16] = {b0.x,b0.y,b0.z,b0.w,b1.x,b1.y,b1.z,b1.w,
                        b2.x,b2.y,b2.z,b2.w,b3.x,b3.y,b3.z,b3.w};
        float2 oa[NK2], ob[NK2];
        rfft16_pair(A, Bv, oa, ob);
#pragma unroll
        for (int k = 0; k < NK2; k++) {
            s1[ph][q][(2 * u) * 9 + k]     = oa[k];
            s1[ph][q][(2 * u + 1) * 9 + k] = ob[k];
        }
    }
    __syncthreads();

    // stage2: thread = (q, k2), both p-parities -> pair-packed planar store
    if (tid < 72) {
        int q = tid & 7, k2 = tid >> 3;
        float2 xin0[16], Xo0[16], xin1[16], Xo1[16];
#pragma unroll
        for (int c1 = 0; c1 < 16; c1++) { xin0[c1] = s1[0][q][c1 * 9 + k2];
                                          xin1[c1] = s1[1][q][c1 * 9 + k2]; }
        cfft16<false>(xin0, Xo0);
        cfft16<false>(xin1, Xo1);
#pragma unroll
        for (int k1 = 0; k1 < 16; k1++) {
            size_t a = ((size_t)(k1 * 9 + k2) * IPD2 + (i << 2) + pp) * FQD + (f << 3) + q;
            g_kf_re[a] = __floats2half2_rn(Xo0[k1].x, Xo1[k1].x);
            g_kf_im[a] = __floats2half2_rn(Xo0[k1].y, Xo1[k1].y);
        }
    }
}

// ============ K3: complex GEMM; K=32 chunks, depth-2, 1 sync/chunk ============
__device__ __forceinline__ void mma16(float* d, const uint32_t* a,
                                      uint32_t b0, uint32_t b1) {
    asm volatile(
        "mma.sync.aligned.m16n8k16.row.col.f32.f16.f16.f32 "
        "{%0,%1,%2,%3}, {%4,%5,%6,%7}, {%8,%9}, {%0,%1,%2,%3};\n"
        : "+f"(d[0]), "+f"(d[1]), "+f"(d[2]), "+f"(d[3])
        : "r"(a[0]), "r"(a[1]), "r"(a[2]), "r"(a[3]), "r"(b0), "r"(b1));
}
__device__ __forceinline__ void cpa16(uint32_t s, const void* g) {
    asm volatile("cp.async.cg.shared.global [%0], [%1], 16;" :: "r"(s), "l"(g));
}

__global__ __launch_bounds__(256) void k3_gemm_hmma() {
    int kidx = blockIdx.x;
    int n0   = blockIdx.y << 7;
    __shared__ __align__(16) __half2 Xs[2][64][36];    // [buf][b][k 0..31 +pad]
    __shared__ __align__(16) __half2 Wr[2][16][132];   // [buf][kp][col]
    __shared__ __align__(16) __half2 Wi[2][16][132];

    int tid = threadIdx.x, wid = tid >> 5, lane = tid & 31;
    int wm = (wid & 3) << 4, wn = (wid >> 2) << 6;
    int gid = lane >> 2, tig = lane & 3;

    const __half2* Xg  = g_xf    + (size_t)kidx * BATCHN * IPD;
    const __half2* Wgr = g_kf_re + (size_t)kidx * IPD2 * FQD + n0;
    const __half2* Wgi = g_kf_im + (size_t)kidx * IPD2 * FQD + n0;

    float accr[8][4], acci[8][4];
#pragma unroll
    for (int j = 0; j < 8; j++)
#pragma unroll
        for (int c = 0; c < 4; c++) { accr[j][c] = 0.f; acci[j][c] = 0.f; }

    // staging maps (per chunk of K=32 -> 16 K-pairs)
    // X: 64 rows x 8 uint4 (32 half2) = 512 uint4 -> 2/thread
    // W: 16 kp x 32 uint4 (128 half2) x 2 planes -> 2+2/thread
    auto stage = [&](int buf, int c) {
        int k0 = c << 5, kp0 = c << 4;
#pragma unroll
        for (int it = 0; it < 2; it++) {
            int u = tid * 2 + it;
            int bb = u >> 3, seg = u & 7;
            cpa16((uint32_t)__cvta_generic_to_shared(&Xs[buf][bb][seg * 4]),
                  Xg + (size_t)bb * IPD + k0 + seg * 4);
        }
#pragma unroll
        for (int it = 0; it < 2; it++) {
            int u = tid + (it << 8);
            int kp = u >> 5, seg = u & 31;
            cpa16((uint32_t)__cvta_generic_to_shared(&Wr[buf][kp][seg * 4]),
                  Wgr + (size_t)(kp0 + kp) * FQD + seg * 4);
            cpa16((uint32_t)__cvta_generic_to_shared(&Wi[buf][kp][seg * 4]),
                  Wgi + (size_t)(kp0 + kp) * FQD + seg * 4);
        }
        asm volatile("cp.async.commit_group;");
    };

    stage(0, 0);

    for (int c = 0; c < 16; c++) {
        asm volatile("cp.async.wait_group 0;");
        __syncthreads();                       // publish chunk c; buf (c+1)&1 free
        if (c + 1 < 16) stage((c + 1) & 1, c + 1);

        int cb = c & 1;
#pragma unroll
        for (int ks = 0; ks < 2; ks++) {
            uint32_t arf[4], aif[4], ainf[4];
#pragma unroll
            for (int m = 0; m < 4; m++) {
                int row  = wm + gid + (m & 1) * 8;
                int kpos = (ks << 4) + 2 * tig + (m >> 1) * 8;
                uint2 lh = *(const uint2*)&Xs[cb][row][kpos];
                arf[m]  = __byte_perm(lh.x, lh.y, 0x5410);
                aif[m]  = __byte_perm(lh.x, lh.y, 0x7632);
                ainf[m] = aif[m] ^ 0x80008000u;
            }
#pragma unroll
            for (int j = 0; j < 8; j++) {
                int col = wn + (j << 3) + gid;
                uint32_t br0 = *(const uint32_t*)&Wr[cb][(ks << 3) + tig][col];
                uint32_t br1 = *(const uint32_t*)&Wr[cb][(ks << 3) + tig + 4][col];
                uint32_t bi0 = *(const uint32_t*)&Wi[cb][(ks << 3) + tig][col];
                uint32_t bi1 = *(const uint32_t*)&Wi[cb][(ks << 3) + tig + 4][col];
                mma16(accr[j], arf,  br0, br1);
                mma16(accr[j], ainf, bi0, bi1);
                mma16(acci[j], arf,  bi0, bi1);
                mma16(acci[j], aif,  br0, br1);
            }
        }
    }

    __half2* Yg = g_yf + (size_t)kidx * BATCHN * FQD;
#pragma unroll
    for (int j = 0; j < 8; j++) {
        int nbase = n0 + wn + (j << 3) + 2 * tig;
        int r0 = wm + gid;
        int r1 = wm + gid + 8;
        __half2 h00 = __floats2half2_rn(accr[j][0], acci[j][0]);
        __half2 h01 = __floats2half2_rn(accr[j][1], acci[j][1]);
        __half2 h10 = __floats2half2_rn(accr[j][2], acci[j][2]);
        __half2 h11 = __floats2half2_rn(accr[j][3], acci[j][3]);
        *(uint2*)&Yg[(size_t)r0 * FQD + nbase] =
            make_uint2(*(uint32_t*)&h00, *(uint32_t*)&h01);
        *(uint2*)&Yg[(size_t)r1 * FQD + nbase] =
            make_uint2(*(uint32_t*)&h10, *(uint32_t*)&h11);
    }
}

// ============ K4: inverse rfft2 + bias; FFT stageA, hoisted stageB ============
__global__ __launch_bounds__(256) void k4_inv(const float* __restrict__ bias,
                                              float* __restrict__ out) {
    int bf = blockIdx.x;
    int b  = bf >> 6;
    int f  = bf & 63;
    __shared__ float2 ys[NP][145];
    __shared__ float2 T[NP][145];
    __shared__ float2 tw[16];
    int tid = threadIdx.x;
    if (tid < 16) tw[tid] = make_float2(CTW16[tid], STW16[tid]);

    for (int idx = tid; idx < NP * NFREQ; idx += 256) {
        int kidx = idx >> 3;
        int q    = idx & 7;
        ys[q][kidx] = __half22float2(
            g_yf[((size_t)kidx * BATCHN + b) * FQD + (f << 3) + q]);
    }
    __syncthreads();

    if (tid < 72) {
        int q = tid & 7, k2 = tid >> 3;
        float2 xin[16], Xo[16];
#pragma unroll
        for (int k1 = 0; k1 < 16; k1++) xin[k1] = ys[q][k1 * 9 + k2];
        cfft16<true>(xin, Xo);
#pragma unroll
        for (int c1 = 0; c1 < 16; c1++) T[q][c1 * 9 + k2] = Xo[c1];
    }
    __syncthreads();

    float bv = bias[f];
    {
        int q  = tid & 7;
        int c2 = (tid >> 3) & 15;
        float wc[9], ws[9];
#pragma unroll
        for (int k2 = 0; k2 < NK2; k2++) {
            float2 w = tw[(k2 * c2) & 15];
            float wt = (k2 == 0 || k2 == 8) ? (1.f / 256.f) : (2.f / 256.f);
            wc[k2] = wt * w.x;
            ws[k2] = wt * w.y;
        }
#pragma unroll
        for (int u = 0; u < 8; u++) {
            int c1 = u * 2 + (tid >> 7);
            float acc = bv;
#pragma unroll
            for (int k2 = 0; k2 < NK2; k2++) {
                float2 v = T[q][c1 * 9 + k2];
                acc += v.x * wc[k2] - v.y * ws[k2];
            }
            out[(size_t)bf * NSYM + u * 256 + tid] = acc;
        }
    }
}

// ============ launch ============
extern "C" void kernel_launch(void* const* d_in, const int* in_sizes, int n_in,
                              void* d_out, int out_size) {
    const float* x    = (const float*)d_in[0];
    const float* kern = (const float*)d_in[1];
    const float* bias = (const float*)d_in[2];
    const void*  pt   = d_in[3];              // int32 or int64 — k0 autodetects
    float*       out  = (float*)d_out;

    k0_pt<<<1, 256>>>(pt);
    k1_xfft<<<BATCHN * INF, 256>>>(x);
    k2_kfft<<<FEAT * INF * 4, 256>>>(kern);
    dim3 g3(NFREQ, FQD / 128);
    k3_gemm_hmma<<<g3, 256>>>();
    k4_inv<<<BATCHN * FEAT, 256>>>(bias, out);
}